// round 12
// baseline (speedup 1.0000x reference)
#include <cuda_runtime.h>
#include <cuda_fp16.h>
#include <math.h>
#include <stdint.h>

#define EPSF 1e-6f
#define NINPUT 64
#define NLAYER 63

// ---------------------------------------------------------------------------
// Persistent scratch (no allocations allowed)
// ---------------------------------------------------------------------------
__device__ __align__(16) float g_lc[512];     // per-layer F constants (63*8 used)
__device__ __align__(16) uint2 g_Pf[1024];    // fp16 P in m16n8k16 B-fragment order

// Layer constants in the constant bank (c-bank operands, zero LSU traffic)
__constant__ float4 c_lc[NLAYER * 2];

// ---------------------------------------------------------------------------
// helpers
// ---------------------------------------------------------------------------
__device__ __forceinline__ float ex2(float t) {
    float r; asm("ex2.approx.ftz.f32 %0, %1;" : "=f"(r) : "f"(t)); return r;
}
__device__ __forceinline__ float lg2(float t) {
    float r; asm("lg2.approx.ftz.f32 %0, %1;" : "=f"(r) : "f"(t)); return r;
}
__device__ __forceinline__ float rcpf(float t) {
    float r; asm("rcp.approx.ftz.f32 %0, %1;" : "=f"(r) : "f"(t)); return r;
}
__device__ __forceinline__ uint32_t f16x2_rn(float lo, float hi) {
    __half2 h = __floats2half2_rn(lo, hi);
    return *reinterpret_cast<uint32_t*>(&h);
}
__device__ __forceinline__ uint32_t ldpack(const float* p) {   // 2 f32 -> f16x2
    float2 f = *reinterpret_cast<const float2*>(p);
    return f16x2_rn(f.x, f.y);
}
__device__ __forceinline__ void mma_fp16(float* d, const uint32_t* a, uint32_t b0,
                                         uint32_t b1) {
    asm("mma.sync.aligned.m16n8k16.row.col.f32.f16.f16.f32 "
        "{%0,%1,%2,%3}, {%4,%5,%6,%7}, {%8,%9}, {%0,%1,%2,%3};"
        : "+f"(d[0]), "+f"(d[1]), "+f"(d[2]), "+f"(d[3])
        : "r"(a[0]), "r"(a[1]), "r"(a[2]), "r"(a[3]), "r"(b0), "r"(b1));
}

// ---------------------------------------------------------------------------
// Setup: u/v-form Sinkhorn (4-way ILP dots) -> fp16 fragment-ordered P + consts
// ---------------------------------------------------------------------------
__global__ __launch_bounds__(256) void setup_kernel(const float* __restrict__ logits,
                                                    const float* __restrict__ weights,
                                                    const float* __restrict__ biases)
{
    __shared__ __align__(16) float M[64 * 68];
    __shared__ __align__(16) float Mt[64 * 68];
    __shared__ __align__(16) float u[64], v[64];
    const int tid = threadIdx.x;

    for (int i = tid; i < 4096; i += 256) {
        int r = i >> 6, c = i & 63;
        float m = __expf(logits[i]);
        M[r * 68 + c]  = m;
        Mt[c * 68 + r] = m;
    }
    if (tid < 64) v[tid] = 1.0f;
    __syncthreads();

    for (int it = 0; it < 20; ++it) {
        if (tid < 64) {                       // u = 1/(M v)
            const float4* mr = reinterpret_cast<const float4*>(&M[tid * 68]);
            const float4* vv = reinterpret_cast<const float4*>(v);
            float s0 = 0.f, s1 = 0.f, s2 = 0.f, s3 = 0.f;
            #pragma unroll
            for (int q = 0; q < 16; ++q) {
                float4 a = mr[q], b = vv[q];
                s0 = fmaf(a.x, b.x, s0); s1 = fmaf(a.y, b.y, s1);
                s2 = fmaf(a.z, b.z, s2); s3 = fmaf(a.w, b.w, s3);
            }
            u[tid] = rcpf((s0 + s1) + (s2 + s3));
        }
        __syncthreads();
        if (tid < 64) {                       // v = 1/(M^T u)
            const float4* mr = reinterpret_cast<const float4*>(&Mt[tid * 68]);
            const float4* uu = reinterpret_cast<const float4*>(u);
            float s0 = 0.f, s1 = 0.f, s2 = 0.f, s3 = 0.f;
            #pragma unroll
            for (int q = 0; q < 16; ++q) {
                float4 a = mr[q], b = uu[q];
                s0 = fmaf(a.x, b.x, s0); s1 = fmaf(a.y, b.y, s1);
                s2 = fmaf(a.z, b.z, s2); s3 = fmaf(a.w, b.w, s3);
            }
            v[tid] = rcpf((s0 + s1) + (s2 + s3));
        }
        __syncthreads();
    }

    // m16n8k16 B-fragment order (R9-verified):
    //   g_Pf[(kt*8+nt)*32 + lane] = { f16x2(P[16kt+2tg][8nt+g], P[16kt+2tg+1][8nt+g]),
    //                                 f16x2(P[16kt+2tg+8][8nt+g], P[16kt+2tg+9][8nt+g]) }
    for (int i = tid; i < 1024; i += 256) {
        int lane = i & 31, ntk = i >> 5;
        int nt = ntk & 7, kt = ntk >> 3;
        int g = lane >> 2, tg = lane & 3;
        int k0 = kt * 16 + 2 * tg, n = nt * 8 + g;
        float p0 = u[k0]     * M[k0 * 68 + n]       * v[n];
        float p1 = u[k0 + 1] * M[(k0 + 1) * 68 + n] * v[n];
        float p8 = u[k0 + 8] * M[(k0 + 8) * 68 + n] * v[n];
        float p9 = u[k0 + 9] * M[(k0 + 9) * 68 + n] * v[n];
        g_Pf[i] = make_uint2(f16x2_rn(p0, p1), f16x2_rn(p8, p9));
    }

    // Per-layer constants: r = A + bw0*xc + bw1*yc + C * exp2(e0*log2(xs)+e1*log2(ys))
    if (tid < NLAYER) {
        float w0 = weights[tid], w1 = 1.0f - w0, a = biases[tid];
        float A, C, cl, e0 = 0.0f, e1 = 0.0f, off;
        if (fabsf(a - 0.5f) < EPSF) {
            A = 0.0f; cl = 1.0f; C = 0.0f; off = 0.0f;
        } else if (a < 0.5f) {
            float ar = fminf(fmaxf(1.0f - a, -1.0f + EPSF), 2.0f - EPSF);
            float p  = sqrtf(3.0f / fmaxf(2.0f - ar, EPSF)) - 1.0f;
            e0 = 2.0f * w0 * p; e1 = 2.0f * w1 * p;
            float bl, bg;
            if      (fabsf(ar - 2.0f) < EPSF) { bl = 0.0f; bg = 0.0f; }
            else if (ar >= 0.75f)             { bl = 0.0f; bg = 1.0f; }
            else if (ar > 0.5f)               { bl = 3.0f - 4.0f * ar; bg = 4.0f * ar - 2.0f; }
            else                              { bl = 1.0f; bg = 0.0f; }
            A = 1.0f - bl; cl = bl; C = -bg; off = 1.0f;
        } else {
            float p = sqrtf(3.0f / fmaxf(2.0f - a, EPSF)) - 1.0f;
            e0 = 2.0f * w0 * p; e1 = 2.0f * w1 * p;
            float bl, bg;
            if      (fabsf(a - 2.0f) < EPSF) { bl = 0.0f; bg = 0.0f; }
            else if (a >= 0.75f)             { bl = 0.0f; bg = 1.0f; }
            else if (a > 0.5f)               { bl = 3.0f - 4.0f * a; bg = 4.0f * a - 2.0f; }
            else                             { bl = 1.0f; bg = 0.0f; }
            A = 0.0f; cl = bl; C = bg; off = 0.0f;
        }
        float* lc = &g_lc[tid * 8];
        lc[0] = cl * w0; lc[1] = cl * w1; lc[2] = A;   lc[3] = C;
        lc[4] = e0;      lc[5] = e1;      lc[6] = off; lc[7] = a;
    }
}

// ---------------------------------------------------------------------------
// Main: PERSISTENT warps, PAIR-tile processing with dual-scan ILP-2.
// Each warp handles tile pairs (t0->buf0, t1->buf1): cp.async both, GEMM A,
// epilogue A->SL0 (alias buf0), GEMM B, epilogue B->SL1 (alias buf1), then a
// dual scan with two independent serial chains per thread. One warp's scan
// now demands ~92% of its SMSP MUFU slot -> scan runs at MUFU throughput,
// not chain latency. Layer constants from c-bank.
// ---------------------------------------------------------------------------
#define XW 72
#define XBUF_W 2304                       // 32*72 words = 9216 B
#define LS 34
#define WSLICE_W (2 * XBUF_W)             // per-warp words (2 buffers)
#define SM_SIZE (4 * 2 * 9216)            // 73728 B per CTA -> 3 CTAs/SM
#define NCTAS 444

__global__ __launch_bounds__(128, 3) void main_kernel(const float* __restrict__ x,
                                                      float* __restrict__ out,
                                                      int batch)
{
    extern __shared__ __align__(16) uint8_t smem[];
    const int tid = threadIdx.x, w = tid >> 5, lane = tid & 31;
    const int g = lane >> 2, tg = lane & 3;

    float* Wbase = reinterpret_cast<float*>(smem) + w * WSLICE_W;
    uint32_t sbase;
    asm("{ .reg .u64 t; cvta.to.shared.u64 t, %1; cvt.u32.u64 %0, t; }"
        : "=r"(sbase) : "l"(Wbase));

    const int ntiles = (batch + 31) >> 5;
    const int warpId = blockIdx.x * 4 + w;
    const int wstride = gridDim.x * 4;
    const size_t f4_limit = (size_t)batch * 16;
    const float4* gx = reinterpret_cast<const float4*>(x);

    // issue one 32-row tile into buffer p (always commits, even if empty)
    auto issue = [&](int tile, int p) {
        if (tile < ntiles) {
            uint32_t dstb = sbase + p * 9216;
            #pragma unroll
            for (int t = 0; t < 16; ++t) {
                int i = lane + t * 32;
                size_t gi = (size_t)tile * 512 + i;
                if (gi < f4_limit) {
                    int r = i >> 4, c4 = i & 15;
                    uint32_t d = dstb + (uint32_t)(r * XW + c4 * 4) * 4;
                    asm volatile("cp.async.cg.shared.global [%0], [%1], 16;"
                                 :: "r"(d), "l"(gx + gi) : "memory");
                }
            }
        }
        asm volatile("cp.async.commit_group;" ::: "memory");
    };

    // one tile's GEMM from buffer Xb into d[2][8][4]
    auto gemm = [&](const float* Xb, float (*d)[8][4]) {
        #pragma unroll
        for (int mt = 0; mt < 2; ++mt)
            #pragma unroll
            for (int nt = 0; nt < 8; ++nt)
                #pragma unroll
                for (int e = 0; e < 4; ++e) d[mt][nt][e] = 0.0f;
        #pragma unroll
        for (int kt = 0; kt < 4; ++kt) {
            const int kc = kt * 16 + 2 * tg;
            uint32_t a[2][4];
            #pragma unroll
            for (int mt = 0; mt < 2; ++mt) {
                int r0 = g + mt * 16;
                a[mt][0] = ldpack(&Xb[r0 * XW + kc]);
                a[mt][1] = ldpack(&Xb[(r0 + 8) * XW + kc]);
                a[mt][2] = ldpack(&Xb[r0 * XW + kc + 8]);
                a[mt][3] = ldpack(&Xb[(r0 + 8) * XW + kc + 8]);
            }
            #pragma unroll
            for (int nt = 0; nt < 8; ++nt) {
                uint2 b = __ldg(&g_Pf[(kt * 8 + nt) * 32 + lane]);
                mma_fp16(d[0][nt], a[0], b.x, b.y);
                mma_fp16(d[1][nt], a[1], b.x, b.y);
            }
        }
    };

    auto epilogue = [&](float* SLb, float (*d)[8][4]) {
        #pragma unroll
        for (int mt = 0; mt < 2; ++mt) {
            int r0 = mt * 16 + g;
            #pragma unroll
            for (int nt = 0; nt < 8; ++nt) {
                int c0 = nt * 8 + tg * 2;
                SLb[c0 * LS + r0]           = d[mt][nt][0];
                SLb[(c0 + 1) * LS + r0]     = d[mt][nt][1];
                SLb[c0 * LS + r0 + 8]       = d[mt][nt][2];
                SLb[(c0 + 1) * LS + r0 + 8] = d[mt][nt][3];
            }
        }
    };

    issue(warpId, 0);
    issue(warpId + wstride, 1);

    float* buf0 = Wbase;
    float* buf1 = Wbase + XBUF_W;

    for (int t0 = warpId; t0 < ntiles; t0 += 2 * wstride) {
        const int t1 = t0 + wstride;
        float d[2][8][4];

        // tile A
        asm volatile("cp.async.wait_group 1;" ::: "memory");
        __syncwarp();
        gemm(buf0, d);
        __syncwarp();
        epilogue(buf0, d);

        // tile B (load may still be landing during GEMM A)
        asm volatile("cp.async.wait_group 0;" ::: "memory");
        __syncwarp();
        gemm(buf1, d);
        __syncwarp();
        epilogue(buf1, d);
        __syncwarp();

        // ---- dual scan: two independent chains per thread ----
        float s0 = buf0[lane];
        float s1 = buf1[lane];
        #pragma unroll
        for (int i = 0; i < NLAYER; ++i) {
            float leaf0 = buf0[(i + 1) * LS + lane];
            float leaf1 = buf1[(i + 1) * LS + lane];
            float4 k0 = c_lc[i * 2];
            float4 k1 = c_lc[i * 2 + 1];

            float xc0 = fminf(fmaxf(s0, EPSF), 1.0f - EPSF);
            float xc1 = fminf(fmaxf(s1, EPSF), 1.0f - EPSF);
            float yc0 = fminf(fmaxf(leaf0, EPSF), 1.0f - EPSF);
            float yc1 = fminf(fmaxf(leaf1, EPSF), 1.0f - EPSF);
            float lgx0 = lg2(fabsf(k1.z - xc0));
            float lgx1 = lg2(fabsf(k1.z - xc1));
            float lgy0 = lg2(fabsf(k1.z - yc0));
            float lgy1 = lg2(fabsf(k1.z - yc1));
            float t0f = fmaf(k1.x, lgx0, k1.y * lgy0);
            float t1f = fmaf(k1.x, lgx1, k1.y * lgy1);
            float gg0 = ex2(t0f);
            float gg1 = ex2(t1f);
            s0 = fmaf(k0.w, gg0, fmaf(k0.y, yc0, fmaf(k0.x, xc0, k0.z)));
            s1 = fmaf(k0.w, gg1, fmaf(k0.y, yc1, fmaf(k0.x, xc1, k0.z)));
        }

        out[t0 * 32 + lane] = s0;
        if (t1 < ntiles) out[t1 * 32 + lane] = s1;

        __syncwarp();            // all lanes done reading SL before refill
        issue(t0 + 2 * wstride, 0);
        issue(t1 + 2 * wstride, 1);
    }
}

// ---------------------------------------------------------------------------
// Launch
// ---------------------------------------------------------------------------
extern "C" void kernel_launch(void* const* d_in, const int* in_sizes, int n_in,
                              void* d_out, int out_size)
{
    const float* x       = (const float*)d_in[0];
    const float* logits  = (const float*)d_in[1];
    const float* weights = (const float*)d_in[2];
    const float* biases  = (const float*)d_in[3];
    float* out = (float*)d_out;

    int batch = in_sizes[0] / NINPUT;

    cudaFuncSetAttribute(main_kernel, cudaFuncAttributeMaxDynamicSharedMemorySize, SM_SIZE);

    setup_kernel<<<1, 256>>>(logits, weights, biases);

    // layer consts -> constant bank (D2D async copy; graph-capturable)
    void* lc_dev = nullptr;
    cudaGetSymbolAddress(&lc_dev, g_lc);
    cudaMemcpyToSymbolAsync(c_lc, lc_dev, NLAYER * 8 * sizeof(float), 0,
                            cudaMemcpyDeviceToDevice, 0);

    main_kernel<<<NCTAS, 128, SM_SIZE>>>(x, out, batch);
}

// round 13
// speedup vs baseline: 1.0062x; 1.0062x over previous
#include <cuda_runtime.h>
#include <cuda_fp16.h>
#include <math.h>
#include <stdint.h>

#define EPSF 1e-6f
#define NINPUT 64
#define NLAYER 63

// ---------------------------------------------------------------------------
// helpers
// ---------------------------------------------------------------------------
__device__ __forceinline__ float ex2(float t) {
    float r; asm("ex2.approx.ftz.f32 %0, %1;" : "=f"(r) : "f"(t)); return r;
}
__device__ __forceinline__ float lg2(float t) {
    float r; asm("lg2.approx.ftz.f32 %0, %1;" : "=f"(r) : "f"(t)); return r;
}
__device__ __forceinline__ float rcpf(float t) {
    float r; asm("rcp.approx.ftz.f32 %0, %1;" : "=f"(r) : "f"(t)); return r;
}
__device__ __forceinline__ uint32_t f16x2_rn(float lo, float hi) {
    __half2 h = __floats2half2_rn(lo, hi);
    return *reinterpret_cast<uint32_t*>(&h);
}
__device__ __forceinline__ uint32_t ldpack(const float* p) {   // 2 f32 -> f16x2
    float2 f = *reinterpret_cast<const float2*>(p);
    return f16x2_rn(f.x, f.y);
}
__device__ __forceinline__ void mma_fp16(float* d, const uint32_t* a, uint32_t b0,
                                         uint32_t b1) {
    asm("mma.sync.aligned.m16n8k16.row.col.f32.f16.f16.f32 "
        "{%0,%1,%2,%3}, {%4,%5,%6,%7}, {%8,%9}, {%0,%1,%2,%3};"
        : "+f"(d[0]), "+f"(d[1]), "+f"(d[2]), "+f"(d[3])
        : "r"(a[0]), "r"(a[1]), "r"(a[2]), "r"(a[3]), "r"(b0), "r"(b1));
}

// ---------------------------------------------------------------------------
// SMEM layout (84 KB dynamic):
//   [0, 73728)       4 warp slices x 2 buffers x 9216 B (X tiles / SL alias)
//                    -- during setup, [0,17920) aliases M[64*68] + u[64] + v[64]
//   [73728, 81920)   sPf: 1024 uint2, fp16 P in m16n8k16 B-fragment order
//   [81920, 83936)   sLC: 63*8 f32 layer constants
// ---------------------------------------------------------------------------
#define XW 72
#define XBUF_W 2304                       // 32*72 words = 9216 B
#define LS 34
#define WSLICE_W (2 * XBUF_W)
#define OFF_PF  73728
#define OFF_LC  81920
#define SM_SIZE 83968
#define NCTAS 296

__global__ __launch_bounds__(128, 2) void fused_kernel(const float* __restrict__ x,
                                                       const float* __restrict__ logits,
                                                       const float* __restrict__ weights,
                                                       const float* __restrict__ biases,
                                                       float* __restrict__ out,
                                                       int batch)
{
    extern __shared__ __align__(16) uint8_t smem[];
    const int tid = threadIdx.x, w = tid >> 5, lane = tid & 31;
    const int g = lane >> 2, tg = lane & 3;

    // ======================= inline setup (per CTA) =======================
    {
        float* M = reinterpret_cast<float*>(smem);            // [64][68]
        float* u = reinterpret_cast<float*>(smem) + 4352;     // 64*68 = 4352
        float* v = u + 64;

        for (int i = tid; i < 4096; i += 128) {
            int r = i >> 6, c = i & 63;
            M[r * 68 + c] = __expf(logits[i]);
        }
        if (tid < 64) v[tid] = 1.0f;
        __syncthreads();

        for (int it = 0; it < 20; ++it) {
            if (tid < 64) {                   // u = 1/(M v): row-contiguous dot
                const float4* mr = reinterpret_cast<const float4*>(&M[tid * 68]);
                const float4* vv = reinterpret_cast<const float4*>(v);
                float s0 = 0.f, s1 = 0.f, s2 = 0.f, s3 = 0.f;
                #pragma unroll
                for (int q = 0; q < 16; ++q) {
                    float4 a = mr[q], b = vv[q];
                    s0 = fmaf(a.x, b.x, s0); s1 = fmaf(a.y, b.y, s1);
                    s2 = fmaf(a.z, b.z, s2); s3 = fmaf(a.w, b.w, s3);
                }
                u[tid] = rcpf((s0 + s1) + (s2 + s3));
            }
            __syncthreads();
            if (tid < 64) {                   // v = 1/(M^T u): column walk
                float s0 = 0.f, s1 = 0.f, s2 = 0.f, s3 = 0.f;
                #pragma unroll
                for (int q = 0; q < 16; ++q) {
                    s0 = fmaf(M[q * 68 + tid],        u[q],      s0);
                    s1 = fmaf(M[(q + 16) * 68 + tid], u[q + 16], s1);
                    s2 = fmaf(M[(q + 32) * 68 + tid], u[q + 32], s2);
                    s3 = fmaf(M[(q + 48) * 68 + tid], u[q + 48], s3);
                }
                v[tid] = rcpf((s0 + s1) + (s2 + s3));
            }
            __syncthreads();
        }

        // fp16 B-fragments (R9-verified order) into sPf
        uint2* sPf = reinterpret_cast<uint2*>(smem + OFF_PF);
        for (int i = tid; i < 1024; i += 128) {
            int ln = i & 31, ntk = i >> 5;
            int nt = ntk & 7, kt = ntk >> 3;
            int gg = ln >> 2, tt = ln & 3;
            int k0 = kt * 16 + 2 * tt, n = nt * 8 + gg;
            float p0 = u[k0]     * M[k0 * 68 + n]       * v[n];
            float p1 = u[k0 + 1] * M[(k0 + 1) * 68 + n] * v[n];
            float p8 = u[k0 + 8] * M[(k0 + 8) * 68 + n] * v[n];
            float p9 = u[k0 + 9] * M[(k0 + 9) * 68 + n] * v[n];
            sPf[i] = make_uint2(f16x2_rn(p0, p1), f16x2_rn(p8, p9));
        }

        // layer constants into sLC
        if (tid < NLAYER) {
            float w0 = weights[tid], w1 = 1.0f - w0, a = biases[tid];
            float A, C, cl, e0 = 0.0f, e1 = 0.0f, off;
            if (fabsf(a - 0.5f) < EPSF) {
                A = 0.0f; cl = 1.0f; C = 0.0f; off = 0.0f;
            } else if (a < 0.5f) {
                float ar = fminf(fmaxf(1.0f - a, -1.0f + EPSF), 2.0f - EPSF);
                float p  = sqrtf(3.0f / fmaxf(2.0f - ar, EPSF)) - 1.0f;
                e0 = 2.0f * w0 * p; e1 = 2.0f * w1 * p;
                float bl, bg;
                if      (fabsf(ar - 2.0f) < EPSF) { bl = 0.0f; bg = 0.0f; }
                else if (ar >= 0.75f)             { bl = 0.0f; bg = 1.0f; }
                else if (ar > 0.5f)               { bl = 3.0f - 4.0f * ar; bg = 4.0f * ar - 2.0f; }
                else                              { bl = 1.0f; bg = 0.0f; }
                A = 1.0f - bl; cl = bl; C = -bg; off = 1.0f;
            } else {
                float p = sqrtf(3.0f / fmaxf(2.0f - a, EPSF)) - 1.0f;
                e0 = 2.0f * w0 * p; e1 = 2.0f * w1 * p;
                float bl, bg;
                if      (fabsf(a - 2.0f) < EPSF) { bl = 0.0f; bg = 0.0f; }
                else if (a >= 0.75f)             { bl = 0.0f; bg = 1.0f; }
                else if (a > 0.5f)               { bl = 3.0f - 4.0f * a; bg = 4.0f * a - 2.0f; }
                else                              { bl = 1.0f; bg = 0.0f; }
                A = 0.0f; cl = bl; C = bg; off = 0.0f;
            }
            float* lc = reinterpret_cast<float*>(smem + OFF_LC) + tid * 8;
            lc[0] = cl * w0; lc[1] = cl * w1; lc[2] = A;   lc[3] = C;
            lc[4] = e0;      lc[5] = e1;      lc[6] = off; lc[7] = a;
        }
        __syncthreads();                       // M region now dead; buffers live
    }

    // ======================= persistent main loop =======================
    const uint2*  sPf = reinterpret_cast<const uint2*>(smem + OFF_PF);
    const float*  sLC = reinterpret_cast<const float*>(smem + OFF_LC);

    float* Wbase = reinterpret_cast<float*>(smem) + w * WSLICE_W;
    uint32_t sbase;
    asm("{ .reg .u64 t; cvta.to.shared.u64 t, %1; cvt.u32.u64 %0, t; }"
        : "=r"(sbase) : "l"(Wbase));

    const int ntiles = (batch + 31) >> 5;
    const int warpId = blockIdx.x * 4 + w;
    const int wstride = gridDim.x * 4;
    const size_t f4_limit = (size_t)batch * 16;
    const float4* gx = reinterpret_cast<const float4*>(x);

    auto issue = [&](int tile, int p) {
        if (tile < ntiles) {
            uint32_t dstb = sbase + p * 9216;
            #pragma unroll
            for (int t = 0; t < 16; ++t) {
                int i = lane + t * 32;
                size_t gi = (size_t)tile * 512 + i;
                if (gi < f4_limit) {
                    int r = i >> 4, c4 = i & 15;
                    uint32_t d = dstb + (uint32_t)(r * XW + c4 * 4) * 4;
                    asm volatile("cp.async.cg.shared.global [%0], [%1], 16;"
                                 :: "r"(d), "l"(gx + gi) : "memory");
                }
            }
        }
        asm volatile("cp.async.commit_group;" ::: "memory");
    };

    auto gemm = [&](const float* Xb, float (*d)[8][4]) {
        #pragma unroll
        for (int mt = 0; mt < 2; ++mt)
            #pragma unroll
            for (int nt = 0; nt < 8; ++nt)
                #pragma unroll
                for (int e = 0; e < 4; ++e) d[mt][nt][e] = 0.0f;
        #pragma unroll
        for (int kt = 0; kt < 4; ++kt) {
            const int kc = kt * 16 + 2 * tg;
            uint32_t a[2][4];
            #pragma unroll
            for (int mt = 0; mt < 2; ++mt) {
                int r0 = g + mt * 16;
                a[mt][0] = ldpack(&Xb[r0 * XW + kc]);
                a[mt][1] = ldpack(&Xb[(r0 + 8) * XW + kc]);
                a[mt][2] = ldpack(&Xb[r0 * XW + kc + 8]);
                a[mt][3] = ldpack(&Xb[(r0 + 8) * XW + kc + 8]);
            }
            #pragma unroll
            for (int nt = 0; nt < 8; ++nt) {
                uint2 b = sPf[(kt * 8 + nt) * 32 + lane];
                mma_fp16(d[0][nt], a[0], b.x, b.y);
                mma_fp16(d[1][nt], a[1], b.x, b.y);
            }
        }
    };

    auto epilogue = [&](float* SLb, float (*d)[8][4]) {
        #pragma unroll
        for (int mt = 0; mt < 2; ++mt) {
            int r0 = mt * 16 + g;
            #pragma unroll
            for (int nt = 0; nt < 8; ++nt) {
                int c0 = nt * 8 + tg * 2;
                SLb[c0 * LS + r0]           = d[mt][nt][0];
                SLb[(c0 + 1) * LS + r0]     = d[mt][nt][1];
                SLb[c0 * LS + r0 + 8]       = d[mt][nt][2];
                SLb[(c0 + 1) * LS + r0 + 8] = d[mt][nt][3];
            }
        }
    };

    issue(warpId, 0);
    issue(warpId + wstride, 1);

    float* buf0 = Wbase;
    float* buf1 = Wbase + XBUF_W;

    for (int t0 = warpId; t0 < ntiles; t0 += 2 * wstride) {
        const int t1 = t0 + wstride;
        float d[2][8][4];

        asm volatile("cp.async.wait_group 1;" ::: "memory");
        __syncwarp();
        gemm(buf0, d);
        __syncwarp();
        epilogue(buf0, d);

        asm volatile("cp.async.wait_group 0;" ::: "memory");
        __syncwarp();
        gemm(buf1, d);
        __syncwarp();
        epilogue(buf1, d);
        __syncwarp();

        // ---- dual scan (ILP-2), consts via uniform LDS.128 ----
        float s0 = buf0[lane];
        float s1 = buf1[lane];
        #pragma unroll
        for (int i = 0; i < NLAYER; ++i) {
            float leaf0 = buf0[(i + 1) * LS + lane];
            float leaf1 = buf1[(i + 1) * LS + lane];
            float4 k0 = *reinterpret_cast<const float4*>(&sLC[i * 8]);
            float4 k1 = *reinterpret_cast<const float4*>(&sLC[i * 8 + 4]);

            float xc0 = fminf(fmaxf(s0, EPSF), 1.0f - EPSF);
            float xc1 = fminf(fmaxf(s1, EPSF), 1.0f - EPSF);
            float yc0 = fminf(fmaxf(leaf0, EPSF), 1.0f - EPSF);
            float yc1 = fminf(fmaxf(leaf1, EPSF), 1.0f - EPSF);
            float lgx0 = lg2(fabsf(k1.z - xc0));
            float lgx1 = lg2(fabsf(k1.z - xc1));
            float lgy0 = lg2(fabsf(k1.z - yc0));
            float lgy1 = lg2(fabsf(k1.z - yc1));
            float t0f = fmaf(k1.x, lgx0, k1.y * lgy0);
            float t1f = fmaf(k1.x, lgx1, k1.y * lgy1);
            float gg0 = ex2(t0f);
            float gg1 = ex2(t1f);
            s0 = fmaf(k0.w, gg0, fmaf(k0.y, yc0, fmaf(k0.x, xc0, k0.z)));
            s1 = fmaf(k0.w, gg1, fmaf(k0.y, yc1, fmaf(k0.x, xc1, k0.z)));
        }

        int r0 = t0 * 32 + lane;
        if (r0 < batch) out[r0] = s0;
        if (t1 < ntiles) {
            int r1 = t1 * 32 + lane;
            if (r1 < batch) out[r1] = s1;
        }

        __syncwarp();
        issue(t0 + 2 * wstride, 0);
        issue(t1 + 2 * wstride, 1);
    }
}

// ---------------------------------------------------------------------------
// Launch: ONE kernel, one graph node.
// ---------------------------------------------------------------------------
extern "C" void kernel_launch(void* const* d_in, const int* in_sizes, int n_in,
                              void* d_out, int out_size)
{
    const float* x       = (const float*)d_in[0];
    const float* logits  = (const float*)d_in[1];
    const float* weights = (const float*)d_in[2];
    const float* biases  = (const float*)d_in[3];
    float* out = (float*)d_out;

    int batch = in_sizes[0] / NINPUT;

    cudaFuncSetAttribute(fused_kernel, cudaFuncAttributeMaxDynamicSharedMemorySize, SM_SIZE);

    fused_kernel<<<NCTAS, 128, SM_SIZE>>>(x, logits, weights, biases, out, batch);
}